// round 2
// baseline (speedup 1.0000x reference)
#include <cuda_runtime.h>

// Problem constants
#define Bz  4
#define NSz 10000
#define NTz 10000
#define Ez  160000
#define Kz  16
#define Dd  128
#define BM  64          // rows per block tile
#define NTHR 256
#define AP  65          // padded pitch for transposed A tile (conflict-free)

// Scratch (allocation-free rule: __device__ globals)
__device__ float g_sproj[(size_t)Bz * NSz * Dd];   // src @ W_s2e
__device__ float g_tproj[(size_t)Bz * NTz * Dd];   // tgt @ W_t2e
__device__ float g_dbond[(size_t)Bz * Ez  * Dd];   // post-LN d_bond (needed by pass 2 gather)

// ---------------- shared helpers ----------------

__device__ __forceinline__ void load_W(float* Ws, const float* __restrict__ W, int tid) {
    float4* dst = (float4*)Ws;
    const float4* src = (const float4*)W;
    #pragma unroll
    for (int i = 0; i < (Dd * Dd / 4) / NTHR; ++i)   // 16 iters
        dst[tid + i * NTHR] = src[tid + i * NTHR];
}

// Load BM x 128 tile of A, transposed into As[k][row] with pitch AP (bank-conflict-free).
__device__ __forceinline__ void load_A_T(float* As, const float* __restrict__ A,
                                         size_t row0, int tid) {
    #pragma unroll
    for (int i = 0; i < (BM * Dd) / NTHR; ++i) {     // 32 iters
        int idx = tid + i * NTHR;
        int r = idx >> 7;
        int k = idx & 127;
        As[k * AP + r] = A[(row0 + r) * Dd + k];
    }
}

// 64x128x128 fp32 GEMM accumulate. Thread owns 8 rows x 4 cols.
// Warp w owns local rows [8w, 8w+8); lane c owns cols [4c, 4c+4).
__device__ __forceinline__ void gemm128(const float* Ws, const float* As,
                                        float acc[8][4], int wrow0, int c4) {
    #pragma unroll 8
    for (int k = 0; k < Dd; ++k) {
        const float4 b4 = *(const float4*)(Ws + k * Dd + c4);
        const float* ar = As + k * AP + wrow0;
        #pragma unroll
        for (int i = 0; i < 8; ++i) {
            float a = ar[i];
            acc[i][0] = fmaf(a, b4.x, acc[i][0]);
            acc[i][1] = fmaf(a, b4.y, acc[i][1]);
            acc[i][2] = fmaf(a, b4.z, acc[i][2]);
            acc[i][3] = fmaf(a, b4.w, acc[i][3]);
        }
    }
}

__device__ __forceinline__ float warp_sum(float v) {
    #pragma unroll
    for (int o = 16; o; o >>= 1) v += __shfl_xor_sync(0xffffffffu, v, o);
    return v;
}

__device__ __forceinline__ float silu(float v) {
    return v * (1.0f / (1.0f + __expf(-v)));
}

// ---------------- kernel 1: both node projections ----------------
// blocks [0,625): src @ W_s2e -> g_sproj ; blocks [625,1250): tgt @ W_t2e -> g_tproj
extern "C" __global__ void __launch_bounds__(NTHR, 2)
proj_kernel(const float* __restrict__ src, const float* __restrict__ tgt,
            const float* __restrict__ W_s2e, const float* __restrict__ W_t2e) {
    extern __shared__ float sm[];
    float* Ws = sm;
    float* As = sm + Dd * Dd;
    int tid = threadIdx.x;

    int blk = blockIdx.x;
    const int NBLK_S = (Bz * NSz) / BM;   // 625
    const float* X; const float* W; float* Y;
    if (blk < NBLK_S) { X = src; W = W_s2e; Y = g_sproj; }
    else              { blk -= NBLK_S; X = tgt; W = W_t2e; Y = g_tproj; }

    size_t row0 = (size_t)blk * BM;
    load_W(Ws, W, tid);
    load_A_T(As, X, row0, tid);
    __syncthreads();

    float acc[8][4] = {};
    int c4 = (tid & 31) * 4, wrow0 = (tid >> 5) * 8;
    gemm128(Ws, As, acc, wrow0, c4);

    #pragma unroll
    for (int i = 0; i < 8; ++i) {
        size_t row = row0 + wrow0 + i;
        *(float4*)(Y + row * Dd + c4) =
            make_float4(acc[i][0], acc[i][1], acc[i][2], acc[i][3]);
    }
}

// ---------------- kernel 2: bond update (the big one) ----------------
// d = bond @ W_e2e + gather(sproj) + gather(tproj); y = LN(silu(d));
// g_dbond = y; out0 = bond + y.
extern "C" __global__ void __launch_bounds__(NTHR, 2)
bond_kernel(const float* __restrict__ bond, const float* __restrict__ W_e2e,
            const int* __restrict__ src_order, const int* __restrict__ tgt_order,
            const float* __restrict__ lg, const float* __restrict__ lb,
            float* __restrict__ out0) {
    extern __shared__ float sm[];
    float* Ws = sm;
    float* As = sm + Dd * Dd;
    int tid = threadIdx.x;
    size_t row0 = (size_t)blockIdx.x * BM;

    load_W(Ws, W_e2e, tid);
    load_A_T(As, bond, row0, tid);
    __syncthreads();

    float acc[8][4] = {};
    int c4 = (tid & 31) * 4, wrow0 = (tid >> 5) * 8;
    gemm128(Ws, As, acc, wrow0, c4);

    float4 g4  = *(const float4*)(lg + c4);
    float4 bb4 = *(const float4*)(lb + c4);

    #pragma unroll
    for (int i = 0; i < 8; ++i) {
        size_t grow = row0 + wrow0 + i;            // flattened (b, e)
        int b = (int)(grow / Ez);
        int e = (int)(grow - (size_t)b * Ez);
        int so = src_order[e];
        int to = tgt_order[e];
        float4 sp = *(const float4*)(g_sproj + ((size_t)b * NSz + so) * Dd + c4);
        float4 tp = *(const float4*)(g_tproj + ((size_t)b * NTz + to) * Dd + c4);

        float u0 = silu(acc[i][0] + sp.x + tp.x);
        float u1 = silu(acc[i][1] + sp.y + tp.y);
        float u2 = silu(acc[i][2] + sp.z + tp.z);
        float u3 = silu(acc[i][3] + sp.w + tp.w);

        float s  = warp_sum(u0 + u1 + u2 + u3);
        float s2 = warp_sum(u0*u0 + u1*u1 + u2*u2 + u3*u3);
        float m   = s  * (1.0f / Dd);
        float var = s2 * (1.0f / Dd) - m * m;
        float rs  = rsqrtf(var + 1e-5f);

        float y0 = (u0 - m) * rs * g4.x + bb4.x;
        float y1 = (u1 - m) * rs * g4.y + bb4.y;
        float y2 = (u2 - m) * rs * g4.z + bb4.z;
        float y3 = (u3 - m) * rs * g4.w + bb4.w;

        *(float4*)(g_dbond + grow * Dd + c4) = make_float4(y0, y1, y2, y3);
        float4 bd = *(const float4*)(bond + grow * Dd + c4);
        *(float4*)(out0 + grow * Dd + c4) =
            make_float4(bd.x + y0, bd.y + y1, bd.z + y2, bd.w + y3);
    }
}

// ---------------- kernel 3: target update ----------------
// br = (1/16) * sum_k coef[t,k] * d_bond[b, edge_order[t,k]];
// d = br @ W_e2t + tgt @ W_t2t; y = LN(silu(d)); out2 = tgt + y.
extern "C" __global__ void __launch_bounds__(NTHR, 2)
tgt_kernel(const float* __restrict__ tgt,
           const float* __restrict__ W_e2t, const float* __restrict__ W_t2t,
           const float* __restrict__ coef, const int* __restrict__ eorder,
           const float* __restrict__ lg, const float* __restrict__ lb,
           float* __restrict__ out2) {
    extern __shared__ float sm[];
    float* Ws = sm;
    float* As = sm + Dd * Dd;
    int tid = threadIdx.x;
    size_t row0 = (size_t)blockIdx.x * BM;

    // Phase A: bond_reduce tile (transposed) + W_e2t
    load_W(Ws, W_e2t, tid);
    #pragma unroll 2
    for (int it = 0; it < (BM * Dd) / NTHR; ++it) {  // 32 iters
        int idx = tid + it * NTHR;
        int r = idx >> 7;
        int j = idx & 127;
        size_t grow = row0 + r;
        int b = (int)(grow / NTz);
        int t = (int)(grow - (size_t)b * NTz);
        const int*   eo = eorder + t * Kz;
        const float* cf = coef   + t * Kz;
        float a = 0.0f;
        #pragma unroll
        for (int k = 0; k < Kz; ++k)
            a = fmaf(cf[k], g_dbond[((size_t)b * Ez + eo[k]) * Dd + j], a);
        As[j * AP + r] = a * (1.0f / Kz);
    }
    __syncthreads();

    float acc[8][4] = {};
    int c4 = (tid & 31) * 4, wrow0 = (tid >> 5) * 8;
    gemm128(Ws, As, acc, wrow0, c4);
    __syncthreads();

    // Phase B: tgt tile + W_t2t, accumulate
    load_W(Ws, W_t2t, tid);
    load_A_T(As, tgt, row0, tid);
    __syncthreads();
    gemm128(Ws, As, acc, wrow0, c4);

    float4 g4  = *(const float4*)(lg + c4);
    float4 bb4 = *(const float4*)(lb + c4);

    #pragma unroll
    for (int i = 0; i < 8; ++i) {
        size_t grow = row0 + wrow0 + i;
        float u0 = silu(acc[i][0]);
        float u1 = silu(acc[i][1]);
        float u2 = silu(acc[i][2]);
        float u3 = silu(acc[i][3]);

        float s  = warp_sum(u0 + u1 + u2 + u3);
        float s2 = warp_sum(u0*u0 + u1*u1 + u2*u2 + u3*u3);
        float m   = s  * (1.0f / Dd);
        float var = s2 * (1.0f / Dd) - m * m;
        float rs  = rsqrtf(var + 1e-5f);

        float y0 = (u0 - m) * rs * g4.x + bb4.x;
        float y1 = (u1 - m) * rs * g4.y + bb4.y;
        float y2 = (u2 - m) * rs * g4.z + bb4.z;
        float y3 = (u3 - m) * rs * g4.w + bb4.w;

        float4 tv = *(const float4*)(tgt + grow * Dd + c4);
        *(float4*)(out2 + grow * Dd + c4) =
            make_float4(tv.x + y0, tv.y + y1, tv.z + y2, tv.w + y3);
    }
}

// ---------------- launcher ----------------
extern "C" void kernel_launch(void* const* d_in, const int* in_sizes, int n_in,
                              void* d_out, int out_size) {
    const float* bond  = (const float*)d_in[0];
    const float* src   = (const float*)d_in[1];
    const float* tgt   = (const float*)d_in[2];
    const float* W_s2e = (const float*)d_in[3];
    const float* W_t2e = (const float*)d_in[4];
    const float* W_e2e = (const float*)d_in[5];
    const float* ln1g  = (const float*)d_in[6];
    const float* ln1b  = (const float*)d_in[7];
    const float* W_e2t = (const float*)d_in[8];
    const float* W_t2t = (const float*)d_in[9];
    const float* ln2g  = (const float*)d_in[10];
    const float* ln2b  = (const float*)d_in[11];
    const float* coef  = (const float*)d_in[12];
    const int*   so    = (const int*)d_in[13];
    const int*   to    = (const int*)d_in[14];
    const int*   eo    = (const int*)d_in[15];

    float* out0 = (float*)d_out;                         // bond + d_bond  [B,E,D]
    float* out1 = out0 + (size_t)Bz * Ez  * Dd;          // src passthrough [B,NS,D]
    float* out2 = out1 + (size_t)Bz * NSz * Dd;          // tgt + d_tgt    [B,NT,D]

    const int smem = (Dd * Dd + Dd * AP) * (int)sizeof(float);   // 98816 B
    cudaFuncSetAttribute(proj_kernel, cudaFuncAttributeMaxDynamicSharedMemorySize, smem);
    cudaFuncSetAttribute(bond_kernel, cudaFuncAttributeMaxDynamicSharedMemorySize, smem);
    cudaFuncSetAttribute(tgt_kernel,  cudaFuncAttributeMaxDynamicSharedMemorySize, smem);

    proj_kernel<<<(Bz * NSz + Bz * NTz) / BM, NTHR, smem>>>(src, tgt, W_s2e, W_t2e);
    bond_kernel<<<(Bz * Ez) / BM, NTHR, smem>>>(bond, W_e2e, so, to, ln1g, ln1b, out0);
    cudaMemcpyAsync(out1, src, (size_t)Bz * NSz * Dd * sizeof(float),
                    cudaMemcpyDeviceToDevice, 0);
    tgt_kernel<<<(Bz * NTz) / BM, NTHR, smem>>>(tgt, W_e2t, W_t2t, coef, eo,
                                                ln2g, ln2b, out2);
}